// round 10
// baseline (speedup 1.0000x reference)
#include <cuda_runtime.h>

#define DIMC 192
#define RR   48
#define BB   4
#define HH   256
#define WW   256
#define HW   (HH * WW)
#define EPSV 1e-5f
#define TROWS 32
#define SPITCH 260   // smem row pitch in floats (256 + 4 pad)

__device__ float g_part[2 * BB * DIMC];      // partial pool sums
__device__ float g_t[BB * RR];               // hidden activations
__device__ float g_wt[BB * DIMC * 4];        // 4 live taps per (b,c)

// ---------------------------------------------------------------------------
// Kernel 1: partial global average pool. Two blocks (512 thr) per channel.
// ---------------------------------------------------------------------------
__global__ void __launch_bounds__(512) pool_kernel(const float* __restrict__ x) {
    const int bc   = blockIdx.x >> 1;
    const int half = blockIdx.x & 1;
    const float4* p = (const float4*)(x + (size_t)bc * HW + (size_t)half * (HW / 2));
    const int n4 = HW / 8;
    float s0 = 0.f, s1 = 0.f;
    for (int i = threadIdx.x; i < n4; i += 1024) {
        float4 a = p[i];
        float4 b = p[i + 512];
        s0 += (a.x + a.y) + (a.z + a.w);
        s1 += (b.x + b.y) + (b.z + b.w);
    }
    float s = s0 + s1;
    #pragma unroll
    for (int o = 16; o > 0; o >>= 1) s += __shfl_xor_sync(0xffffffffu, s, o);
    __shared__ float sm[16];
    if ((threadIdx.x & 31) == 0) sm[threadIdx.x >> 5] = s;
    __syncthreads();
    if (threadIdx.x == 0) {
        float t = 0.f;
        #pragma unroll
        for (int i = 0; i < 16; i++) t += sm[i];
        g_part[blockIdx.x] = t;
    }
}

// ---------------------------------------------------------------------------
// Kernel 2a: t = relu(BN(pooled @ w1^T)). Warp per (j,b). 192 warps = 24 blocks.
// ---------------------------------------------------------------------------
__global__ void __launch_bounds__(256) wgen_a_kernel(
    const float* __restrict__ w1,
    const float* __restrict__ gamma, const float* __restrict__ beta,
    const float* __restrict__ rmean, const float* __restrict__ rvar)
{
    const int gw   = blockIdx.x * 8 + (threadIdx.x >> 5);   // 0..191
    const int lane = threadIdx.x & 31;
    const int j    = gw % RR;
    const int b    = gw / RR;

    float acc = 0.f;
    #pragma unroll
    for (int k = 0; k < DIMC / 32; k++) {
        const int c = lane + k * 32;
        const float pooled = (g_part[2 * (b * DIMC + c)] + g_part[2 * (b * DIMC + c) + 1])
                             * (1.0f / (float)HW);
        acc = fmaf(w1[j * DIMC + c], pooled, acc);
    }
    #pragma unroll
    for (int o = 16; o > 0; o >>= 1) acc += __shfl_xor_sync(0xffffffffu, acc, o);
    if (lane == 0) {
        float v = gamma[j] * (acc - rmean[j]) * rsqrtf(rvar[j] + EPSV) + beta[j];
        g_t[b * RR + j] = fmaxf(v, 0.f);
    }
}

// ---------------------------------------------------------------------------
// Kernel 2b: taps = t @ w2^T + b2 (masked: 4 taps per channel).
// Warp per output. 3072 outputs = 384 blocks x 8 warps.
// ---------------------------------------------------------------------------
__global__ void __launch_bounds__(256) wgen_b_kernel(
    const float* __restrict__ w2, const float* __restrict__ b2)
{
    const int idx  = blockIdx.x * 8 + (threadIdx.x >> 5);   // 0..3071
    const int lane = threadIdx.x & 31;
    const int b    = idx / (DIMC * 4);
    const int rem  = idx % (DIMC * 4);
    const int c    = rem >> 2;
    const int tap  = rem & 3;
    const int o    = c * 9 + tap;

    const float* tv = g_t + b * RR;
    const float* wr = w2 + o * RR;
    float acc = tv[lane] * wr[lane];
    if (lane < RR - 32) acc = fmaf(tv[lane + 32], wr[lane + 32], acc);
    #pragma unroll
    for (int off = 16; off > 0; off >>= 1) acc += __shfl_xor_sync(0xffffffffu, acc, off);
    if (lane == 0) g_wt[(b * DIMC + c) * 4 + tap] = acc + b2[o];
}

// ---------------------------------------------------------------------------
// Kernel 3: 4-tap masked depthwise stencil + bias via smem row tile.
// 512 threads, 32 output rows (+1 halo). Halo reads are ALIGNED float4 LDS
// (conflict-free); boundary components masked by selects.
// grid = (8, 768)
// ---------------------------------------------------------------------------
__global__ void __launch_bounds__(512) conv_kernel(
    const float* __restrict__ x, const float* __restrict__ bias,
    float* __restrict__ out)
{
    __shared__ float s_raw[4 + (TROWS + 1) * SPITCH];
    float* sb = s_raw + 4;                      // front pad for x4==0 reads

    const int bc  = blockIdx.y;
    const int c   = bc % DIMC;
    const int r0  = blockIdx.x * TROWS;
    const int tid = threadIdx.x;

    const float w0 = g_wt[bc * 4 + 0];
    const float w1 = g_wt[bc * 4 + 1];
    const float w2 = g_wt[bc * 4 + 2];
    const float w3 = g_wt[bc * 4 + 3];
    const float bv = bias[c];

    const float* in = x + (size_t)bc * HW;

    // Load 33 rows (r0-1 .. r0+31), float4-coalesced, streaming.
    const int NL = (TROWS + 1) * (WW / 4);      // 2112 float4
    #pragma unroll 5
    for (int L = tid; L < NL; L += 512) {
        const int srow  = L >> 6;               // 0..32
        const int scol4 = (L & 63) << 2;
        const int grow  = r0 - 1 + srow;
        float4 v = make_float4(0.f, 0.f, 0.f, 0.f);
        if (grow >= 0)
            v = __ldcs((const float4*)(in + (size_t)grow * WW + scol4));
        *(float4*)&sb[srow * SPITCH + scol4] = v;
    }
    __syncthreads();

    const int col4 = tid & 63;
    const int x4   = col4 << 2;
    const int rowb = tid >> 6;                  // 0..7
    const bool has_l = (x4 > 0);
    const bool has_r = (x4 + 4 < WW);
    float* ot = out + (size_t)bc * HW;

    #pragma unroll
    for (int i = 0; i < 4; i++) {
        const int r = rowb + i * 8;             // 0..31: output row r0+r
        const float* pr_ = &sb[r * SPITCH];     // prev row (global r0+r-1)
        const float* cu_ = pr_ + SPITCH;

        float4 pv = *(const float4*)&pr_[x4];
        float4 pm = *(const float4*)&pr_[x4 - 4];   // front/row pad keeps in-bounds
        float4 pp = *(const float4*)&pr_[x4 + 4];
        float4 cm = *(const float4*)&cu_[x4 - 4];
        float4 cv = *(const float4*)&cu_[x4];

        const float pl = has_l ? pm.w : 0.f;
        const float pq = has_r ? pp.x : 0.f;
        const float cl = has_l ? cm.w : 0.f;

        float4 o;
        o.x = fmaf(w0, pl,   fmaf(w1, pv.x, fmaf(w2, pv.y, fmaf(w3, cl,   bv))));
        o.y = fmaf(w0, pv.x, fmaf(w1, pv.y, fmaf(w2, pv.z, fmaf(w3, cv.x, bv))));
        o.z = fmaf(w0, pv.y, fmaf(w1, pv.z, fmaf(w2, pv.w, fmaf(w3, cv.y, bv))));
        o.w = fmaf(w0, pv.z, fmaf(w1, pv.w, fmaf(w2, pq,   fmaf(w3, cv.z, bv))));

        __stcs((float4*)(ot + (size_t)(r0 + r) * WW + x4), o);
    }
}

// ---------------------------------------------------------------------------
extern "C" void kernel_launch(void* const* d_in, const int* in_sizes, int n_in,
                              void* d_out, int out_size)
{
    const float* x     = (const float*)d_in[0];
    const float* w1    = (const float*)d_in[1];
    const float* gamma = (const float*)d_in[2];
    const float* beta  = (const float*)d_in[3];
    const float* rmean = (const float*)d_in[4];
    const float* rvar  = (const float*)d_in[5];
    const float* w2    = (const float*)d_in[6];
    const float* b2    = (const float*)d_in[7];
    const float* bias  = (const float*)d_in[8];
    float* out = (float*)d_out;

    pool_kernel<<<2 * BB * DIMC, 512>>>(x);
    wgen_a_kernel<<<24, 256>>>(w1, gamma, beta, rmean, rvar);
    wgen_b_kernel<<<384, 256>>>(w2, b2);
    dim3 grd(HH / TROWS, BB * DIMC);
    conv_kernel<<<grd, 512>>>(x, bias, out);
}

// round 12
// speedup vs baseline: 1.1060x; 1.1060x over previous
#include <cuda_runtime.h>

#define DIMC 192
#define RR   48
#define BB   4
#define HH   256
#define WW   256
#define HW   (HH * WW)
#define EPSV 1e-5f
#define RPW  16     // rows per warp in conv

__device__ float g_part[2 * BB * DIMC];      // partial pool sums
__device__ float g_t[BB * RR];               // hidden activations
__device__ float g_wt[BB * DIMC * 4];        // 4 live taps per (b,c)

// ---------------------------------------------------------------------------
// Kernel 1: partial global average pool. Two blocks (512 thr) per channel.
// ---------------------------------------------------------------------------
__global__ void __launch_bounds__(512) pool_kernel(const float* __restrict__ x) {
    const int bc   = blockIdx.x >> 1;
    const int half = blockIdx.x & 1;
    const float4* p = (const float4*)(x + (size_t)bc * HW + (size_t)half * (HW / 2));
    const int n4 = HW / 8;
    float s0 = 0.f, s1 = 0.f;
    for (int i = threadIdx.x; i < n4; i += 1024) {
        float4 a = p[i];
        float4 b = p[i + 512];
        s0 += (a.x + a.y) + (a.z + a.w);
        s1 += (b.x + b.y) + (b.z + b.w);
    }
    float s = s0 + s1;
    #pragma unroll
    for (int o = 16; o > 0; o >>= 1) s += __shfl_xor_sync(0xffffffffu, s, o);
    __shared__ float sm[16];
    if ((threadIdx.x & 31) == 0) sm[threadIdx.x >> 5] = s;
    __syncthreads();
    if (threadIdx.x == 0) {
        float t = 0.f;
        #pragma unroll
        for (int i = 0; i < 16; i++) t += sm[i];
        g_part[blockIdx.x] = t;
    }
}

// ---------------------------------------------------------------------------
// Kernel 2a: t = relu(BN(pooled @ w1^T)). Warp per (j,b).
// ---------------------------------------------------------------------------
__global__ void __launch_bounds__(256) wgen_a_kernel(
    const float* __restrict__ w1,
    const float* __restrict__ gamma, const float* __restrict__ beta,
    const float* __restrict__ rmean, const float* __restrict__ rvar)
{
    const int gw   = blockIdx.x * 8 + (threadIdx.x >> 5);   // 0..191
    const int lane = threadIdx.x & 31;
    const int j    = gw % RR;
    const int b    = gw / RR;

    float acc = 0.f;
    #pragma unroll
    for (int k = 0; k < DIMC / 32; k++) {
        const int c = lane + k * 32;
        const float pooled = (g_part[2 * (b * DIMC + c)] + g_part[2 * (b * DIMC + c) + 1])
                             * (1.0f / (float)HW);
        acc = fmaf(w1[j * DIMC + c], pooled, acc);
    }
    #pragma unroll
    for (int o = 16; o > 0; o >>= 1) acc += __shfl_xor_sync(0xffffffffu, acc, o);
    if (lane == 0) {
        float v = gamma[j] * (acc - rmean[j]) * rsqrtf(rvar[j] + EPSV) + beta[j];
        g_t[b * RR + j] = fmaxf(v, 0.f);
    }
}

// ---------------------------------------------------------------------------
// Kernel 2b: taps = t @ w2^T + b2 (masked: 4 taps per channel). Warp/output.
// ---------------------------------------------------------------------------
__global__ void __launch_bounds__(256) wgen_b_kernel(
    const float* __restrict__ w2, const float* __restrict__ b2)
{
    const int idx  = blockIdx.x * 8 + (threadIdx.x >> 5);   // 0..3071
    const int lane = threadIdx.x & 31;
    const int b    = idx / (DIMC * 4);
    const int rem  = idx % (DIMC * 4);
    const int c    = rem >> 2;
    const int tap  = rem & 3;
    const int o    = c * 9 + tap;

    const float* tv = g_t + b * RR;
    const float* wr = w2 + o * RR;
    float acc = tv[lane] * wr[lane];
    if (lane < RR - 32) acc = fmaf(tv[lane + 32], wr[lane + 32], acc);
    #pragma unroll
    for (int off = 16; off > 0; off >>= 1) acc += __shfl_xor_sync(0xffffffffu, acc, off);
    if (lane == 0) g_wt[(b * DIMC + c) * 4 + tap] = acc + b2[o];
}

// ---------------------------------------------------------------------------
// Kernel 3: 4-tap masked depthwise stencil + bias. NO shared memory.
// Warp owns a full 256-px row (lane = 8 px); marches RPW rows, prev row
// rolls in registers; horizontal halos via intra-warp shuffles.
//   out[y][x] = w0*p[x-1] + w1*p[x] + w2*p[x+1] + w3*c[x-1] + bias
// Block = 256 thr (8 warps). grid = 768 * (256/RPW) / 8 warps.
// ---------------------------------------------------------------------------
__global__ void __launch_bounds__(256) conv_kernel(
    const float* __restrict__ x, const float* __restrict__ bias,
    float* __restrict__ out)
{
    const int lane = threadIdx.x & 31;
    const int gw   = blockIdx.x * 8 + (threadIdx.x >> 5);
    const int RBPC = HH / RPW;                  // 16 row-blocks per channel
    const int bc   = gw / RBPC;
    const int y0   = (gw % RBPC) * RPW;
    const int x8   = lane * 8;

    const float w0 = g_wt[bc * 4 + 0];
    const float w1 = g_wt[bc * 4 + 1];
    const float w2 = g_wt[bc * 4 + 2];
    const float w3 = g_wt[bc * 4 + 3];
    const float bv = bias[bc % DIMC];

    const float* in = x   + (size_t)bc * HW;
    float*       ot = out + (size_t)bc * HW;

    // prev row registers + its halo scalars
    float4 pl4, ph4;                            // p[x8..x8+3], p[x8+4..x8+7]
    float  ppl, ppr;                            // p[x8-1], p[x8+8]
    if (y0 > 0) {
        const float* pr = in + (size_t)(y0 - 1) * WW + x8;
        pl4 = __ldcs((const float4*)pr);
        ph4 = __ldcs((const float4*)(pr + 4));
        ppl = __shfl_up_sync(0xffffffffu, ph4.w, 1);
        ppr = __shfl_down_sync(0xffffffffu, pl4.x, 1);
        if (lane == 0)  ppl = 0.f;
        if (lane == 31) ppr = 0.f;
    } else {
        pl4 = make_float4(0.f, 0.f, 0.f, 0.f);
        ph4 = pl4; ppl = 0.f; ppr = 0.f;
    }

    #pragma unroll
    for (int i = 0; i < RPW; i++) {
        const int y = y0 + i;
        const float* cr = in + (size_t)y * WW + x8;
        float4 cl4 = __ldcs((const float4*)cr);
        float4 ch4 = __ldcs((const float4*)(cr + 4));

        float cml = __shfl_up_sync(0xffffffffu, ch4.w, 1);    // c[x8-1]
        float crr = __shfl_down_sync(0xffffffffu, cl4.x, 1);  // c[x8+8]
        if (lane == 0)  cml = 0.f;
        if (lane == 31) crr = 0.f;

        float4 ol, oh;
        ol.x = fmaf(w0, ppl,   fmaf(w1, pl4.x, fmaf(w2, pl4.y, fmaf(w3, cml,   bv))));
        ol.y = fmaf(w0, pl4.x, fmaf(w1, pl4.y, fmaf(w2, pl4.z, fmaf(w3, cl4.x, bv))));
        ol.z = fmaf(w0, pl4.y, fmaf(w1, pl4.z, fmaf(w2, pl4.w, fmaf(w3, cl4.y, bv))));
        ol.w = fmaf(w0, pl4.z, fmaf(w1, pl4.w, fmaf(w2, ph4.x, fmaf(w3, cl4.z, bv))));
        oh.x = fmaf(w0, pl4.w, fmaf(w1, ph4.x, fmaf(w2, ph4.y, fmaf(w3, cl4.w, bv))));
        oh.y = fmaf(w0, ph4.x, fmaf(w1, ph4.y, fmaf(w2, ph4.z, fmaf(w3, ch4.x, bv))));
        oh.z = fmaf(w0, ph4.y, fmaf(w1, ph4.z, fmaf(w2, ph4.w, fmaf(w3, ch4.y, bv))));
        oh.w = fmaf(w0, ph4.z, fmaf(w1, ph4.w, fmaf(w2, ppr,   fmaf(w3, ch4.z, bv))));

        float* po = ot + (size_t)y * WW + x8;
        __stcs((float4*)po,       ol);
        __stcs((float4*)(po + 4), oh);

        pl4 = cl4; ph4 = ch4; ppl = cml; ppr = crr;
    }
}

// ---------------------------------------------------------------------------
extern "C" void kernel_launch(void* const* d_in, const int* in_sizes, int n_in,
                              void* d_out, int out_size)
{
    const float* x     = (const float*)d_in[0];
    const float* w1    = (const float*)d_in[1];
    const float* gamma = (const float*)d_in[2];
    const float* beta  = (const float*)d_in[3];
    const float* rmean = (const float*)d_in[4];
    const float* rvar  = (const float*)d_in[5];
    const float* w2    = (const float*)d_in[6];
    const float* b2    = (const float*)d_in[7];
    const float* bias  = (const float*)d_in[8];
    float* out = (float*)d_out;

    pool_kernel<<<2 * BB * DIMC, 512>>>(x);
    wgen_a_kernel<<<24, 256>>>(w1, gamma, beta, rmean, rvar);
    wgen_b_kernel<<<384, 256>>>(w2, b2);
    const int nwarps = (BB * DIMC) * (HH / RPW);      // 12288
    conv_kernel<<<nwarps / 8, 256>>>(x, bias, out);
}

// round 16
// speedup vs baseline: 1.1107x; 1.0042x over previous
#include <cuda_runtime.h>

#define DIMC 192
#define RR   48
#define BB   4
#define HH   256
#define WW   256
#define HW   (HH * WW)
#define EPSV 1e-5f
#define RPW  16     // rows per warp in conv

__device__ float g_part[2 * BB * DIMC];      // partial pool sums
__device__ float g_t[BB * RR];               // hidden activations
__device__ float g_wt[BB * DIMC * 4];        // 4 live taps per (b,c)

// ---------------------------------------------------------------------------
// Kernel 1: partial global average pool. Two blocks (512 thr) per channel.
// ---------------------------------------------------------------------------
__global__ void __launch_bounds__(512) pool_kernel(const float* __restrict__ x) {
    const int bc   = blockIdx.x >> 1;
    const int half = blockIdx.x & 1;
    const float4* p = (const float4*)(x + (size_t)bc * HW + (size_t)half * (HW / 2));
    const int n4 = HW / 8;
    float s0 = 0.f, s1 = 0.f;
    for (int i = threadIdx.x; i < n4; i += 1024) {
        float4 a = p[i];
        float4 b = p[i + 512];
        s0 += (a.x + a.y) + (a.z + a.w);
        s1 += (b.x + b.y) + (b.z + b.w);
    }
    float s = s0 + s1;
    #pragma unroll
    for (int o = 16; o > 0; o >>= 1) s += __shfl_xor_sync(0xffffffffu, s, o);
    __shared__ float sm[16];
    if ((threadIdx.x & 31) == 0) sm[threadIdx.x >> 5] = s;
    __syncthreads();
    if (threadIdx.x == 0) {
        float t = 0.f;
        #pragma unroll
        for (int i = 0; i < 16; i++) t += sm[i];
        g_part[blockIdx.x] = t;
    }
}

// ---------------------------------------------------------------------------
// Kernel 2a: t = relu(BN(pooled @ w1^T)). Warp per (j,b).
// ---------------------------------------------------------------------------
__global__ void __launch_bounds__(256) wgen_a_kernel(
    const float* __restrict__ w1,
    const float* __restrict__ gamma, const float* __restrict__ beta,
    const float* __restrict__ rmean, const float* __restrict__ rvar)
{
    const int gw   = blockIdx.x * 8 + (threadIdx.x >> 5);   // 0..191
    const int lane = threadIdx.x & 31;
    const int j    = gw % RR;
    const int b    = gw / RR;

    float acc = 0.f;
    #pragma unroll
    for (int k = 0; k < DIMC / 32; k++) {
        const int c = lane + k * 32;
        const float pooled = (g_part[2 * (b * DIMC + c)] + g_part[2 * (b * DIMC + c) + 1])
                             * (1.0f / (float)HW);
        acc = fmaf(w1[j * DIMC + c], pooled, acc);
    }
    #pragma unroll
    for (int o = 16; o > 0; o >>= 1) acc += __shfl_xor_sync(0xffffffffu, acc, o);
    if (lane == 0) {
        float v = gamma[j] * (acc - rmean[j]) * rsqrtf(rvar[j] + EPSV) + beta[j];
        g_t[b * RR + j] = fmaxf(v, 0.f);
    }
}

// ---------------------------------------------------------------------------
// Kernel 2b: taps = t @ w2^T + b2 (masked: 4 taps per channel). Warp/output.
// ---------------------------------------------------------------------------
__global__ void __launch_bounds__(256) wgen_b_kernel(
    const float* __restrict__ w2, const float* __restrict__ b2)
{
    const int idx  = blockIdx.x * 8 + (threadIdx.x >> 5);   // 0..3071
    const int lane = threadIdx.x & 31;
    const int b    = idx / (DIMC * 4);
    const int rem  = idx % (DIMC * 4);
    const int c    = rem >> 2;
    const int tap  = rem & 3;
    const int o    = c * 9 + tap;

    const float* tv = g_t + b * RR;
    const float* wr = w2 + o * RR;
    float acc = tv[lane] * wr[lane];
    if (lane < RR - 32) acc = fmaf(tv[lane + 32], wr[lane + 32], acc);
    #pragma unroll
    for (int off = 16; off > 0; off >>= 1) acc += __shfl_xor_sync(0xffffffffu, acc, off);
    if (lane == 0) g_wt[(b * DIMC + c) * 4 + tap] = acc + b2[o];
}

// ---------------------------------------------------------------------------
// Kernel 3: 4-tap masked depthwise stencil + bias. NO shared memory.
// Warp owns a full 256-px row (lane = 8 px); marches RPW rows; prev row rolls
// in registers; horizontal halos via intra-warp shuffles.
// REVERSED traversal (high bc first) to hit x still resident in L2 from pool.
// ---------------------------------------------------------------------------
__global__ void __launch_bounds__(256) conv_kernel(
    const float* __restrict__ x, const float* __restrict__ bias,
    float* __restrict__ out)
{
    const int lane = threadIdx.x & 31;
    const int RBPC = HH / RPW;                  // 16 row-blocks per channel
    const int NW   = BB * DIMC * RBPC;          // 12288 warps total
    const int gw   = (NW - 1) - (blockIdx.x * 8 + (threadIdx.x >> 5));
    const int bc   = gw / RBPC;
    const int y0   = (gw % RBPC) * RPW;
    const int x8   = lane * 8;

    const float w0 = g_wt[bc * 4 + 0];
    const float w1 = g_wt[bc * 4 + 1];
    const float w2 = g_wt[bc * 4 + 2];
    const float w3 = g_wt[bc * 4 + 3];
    const float bv = bias[bc % DIMC];

    const float* in = x   + (size_t)bc * HW;
    float*       ot = out + (size_t)bc * HW;

    // prev row registers + its halo scalars
    float4 pl4, ph4;                            // p[x8..x8+3], p[x8+4..x8+7]
    float  ppl, ppr;                            // p[x8-1], p[x8+8]
    if (y0 > 0) {
        const float* pr = in + (size_t)(y0 - 1) * WW + x8;
        pl4 = __ldcs((const float4*)pr);
        ph4 = __ldcs((const float4*)(pr + 4));
        ppl = __shfl_up_sync(0xffffffffu, ph4.w, 1);
        ppr = __shfl_down_sync(0xffffffffu, pl4.x, 1);
        if (lane == 0)  ppl = 0.f;
        if (lane == 31) ppr = 0.f;
    } else {
        pl4 = make_float4(0.f, 0.f, 0.f, 0.f);
        ph4 = pl4; ppl = 0.f; ppr = 0.f;
    }

    #pragma unroll
    for (int i = 0; i < RPW; i++) {
        const int y = y0 + i;
        const float* cr = in + (size_t)y * WW + x8;
        float4 cl4 = __ldcs((const float4*)cr);
        float4 ch4 = __ldcs((const float4*)(cr + 4));

        float cml = __shfl_up_sync(0xffffffffu, ch4.w, 1);    // c[x8-1]
        float crr = __shfl_down_sync(0xffffffffu, cl4.x, 1);  // c[x8+8]
        if (lane == 0)  cml = 0.f;
        if (lane == 31) crr = 0.f;

        float4 ol, oh;
        ol.x = fmaf(w0, ppl,   fmaf(w1, pl4.x, fmaf(w2, pl4.y, fmaf(w3, cml,   bv))));
        ol.y = fmaf(w0, pl4.x, fmaf(w1, pl4.y, fmaf(w2, pl4.z, fmaf(w3, cl4.x, bv))));
        ol.z = fmaf(w0, pl4.y, fmaf(w1, pl4.z, fmaf(w2, pl4.w, fmaf(w3, cl4.y, bv))));
        ol.w = fmaf(w0, pl4.z, fmaf(w1, pl4.w, fmaf(w2, ph4.x, fmaf(w3, cl4.z, bv))));
        oh.x = fmaf(w0, pl4.w, fmaf(w1, ph4.x, fmaf(w2, ph4.y, fmaf(w3, cl4.w, bv))));
        oh.y = fmaf(w0, ph4.x, fmaf(w1, ph4.y, fmaf(w2, ph4.z, fmaf(w3, ch4.x, bv))));
        oh.z = fmaf(w0, ph4.y, fmaf(w1, ph4.z, fmaf(w2, ph4.w, fmaf(w3, ch4.y, bv))));
        oh.w = fmaf(w0, ph4.z, fmaf(w1, ph4.w, fmaf(w2, ppr,   fmaf(w3, ch4.z, bv))));

        float* po = ot + (size_t)y * WW + x8;
        __stcs((float4*)po,       ol);
        __stcs((float4*)(po + 4), oh);

        pl4 = cl4; ph4 = ch4; ppl = cml; ppr = crr;
    }
}

// ---------------------------------------------------------------------------
extern "C" void kernel_launch(void* const* d_in, const int* in_sizes, int n_in,
                              void* d_out, int out_size)
{
    const float* x     = (const float*)d_in[0];
    const float* w1    = (const float*)d_in[1];
    const float* gamma = (const float*)d_in[2];
    const float* beta  = (const float*)d_in[3];
    const float* rmean = (const float*)d_in[4];
    const float* rvar  = (const float*)d_in[5];
    const float* w2    = (const float*)d_in[6];
    const float* b2    = (const float*)d_in[7];
    const float* bias  = (const float*)d_in[8];
    float* out = (float*)d_out;

    pool_kernel<<<2 * BB * DIMC, 512>>>(x);
    wgen_a_kernel<<<24, 256>>>(w1, gamma, beta, rmean, rvar);
    wgen_b_kernel<<<384, 256>>>(w2, b2);
    const int nwarps = (BB * DIMC) * (HH / RPW);      // 12288
    conv_kernel<<<nwarps / 8, 256>>>(x, bias, out);
}